// round 5
// baseline (speedup 1.0000x reference)
#include <cuda_runtime.h>
#include <cuda_bf16.h>
#include <cstdint>

// Problem constants (DiffusionConv: N=50000, E=800000, C=64, K=3)
#define NMAX 50000
#define EMAX 800000
#define C    64

// -------- device scratch (no allocs allowed) --------
__device__ float g_T1[NMAX * C];
__device__ float g_T2[NMAX * C];
__device__ float g_T3[NMAX * C];
__device__ float g_deg[NMAX];
__device__ float g_dinv[NMAX];
__device__ float g_norm[EMAX];
__device__ float g_W[4 * C * C];   // W0=Tf0, W1=Tb0+Tb1, W2=Tf1+Tb2, W3=Tf2

// -------- zero scratch (T1,T2,T3 accumulate via atomics; deg via atomics) ----
__global__ void zero_kernel(int n_nodes) {
    int per_buf = n_nodes * C / 4;        // float4 per buffer
    int total4 = 3 * per_buf;
    for (int i = blockIdx.x * blockDim.x + threadIdx.x; i < total4;
         i += gridDim.x * blockDim.x) {
        int buf = i / per_buf;
        int off = i - buf * per_buf;
        float4 z = make_float4(0.f, 0.f, 0.f, 0.f);
        if (buf == 0)      reinterpret_cast<float4*>(g_T1)[off] = z;
        else if (buf == 1) reinterpret_cast<float4*>(g_T2)[off] = z;
        else               reinterpret_cast<float4*>(g_T3)[off] = z;
    }
    for (int i = blockIdx.x * blockDim.x + threadIdx.x; i < n_nodes;
         i += gridDim.x * blockDim.x)
        g_deg[i] = 0.f;
}

// -------- degree: deg[row[e]] += w[e] --------
__global__ void deg_kernel(const int* __restrict__ row,
                           const float* __restrict__ w, int E) {
    int e = blockIdx.x * blockDim.x + threadIdx.x;
    if (e < E) atomicAdd(&g_deg[row[e]], w[e]);
}

// -------- deg^{-1/2} --------
__global__ void dinv_kernel(int n_nodes) {
    int i = blockIdx.x * blockDim.x + threadIdx.x;
    if (i < n_nodes) {
        float d = g_deg[i];
        g_dinv[i] = (d > 0.f) ? rsqrtf(d) : 0.f;
    }
}

// -------- per-edge norm = dinv[row]*w*dinv[col] --------
__global__ void norm_kernel(const int* __restrict__ row,
                            const int* __restrict__ col,
                            const float* __restrict__ w, int E) {
    int e = blockIdx.x * blockDim.x + threadIdx.x;
    if (e < E) g_norm[e] = g_dinv[row[e]] * w[e] * g_dinv[col[e]];
}

// -------- combine thetas: W0=Tf0, W1=Tb0+Tb1, W2=Tf1+Tb2, W3=Tf2 --------
__global__ void wprep_kernel(const float* __restrict__ tf,
                             const float* __restrict__ tb) {
    int i = blockIdx.x * blockDim.x + threadIdx.x;   // 0..4095
    if (i < C * C) {
        g_W[0 * C * C + i] = tf[0 * C * C + i];
        g_W[1 * C * C + i] = tb[0 * C * C + i] + tb[1 * C * C + i];
        g_W[2 * C * C + i] = tf[1 * C * C + i] + tb[2 * C * C + i];
        g_W[3 * C * C + i] = tf[2 * C * C + i];
    }
}

// -------- propagate: dst[row[e]] += norm[e] * src[col[e]]  (vector RED) ------
// 16 threads per edge, each handles one float4 (4 channels).
// CRITICAL: src/dst scratch buffers are selected INSIDE device code via `step`
// — __device__ symbols must never be passed as host-side kernel arguments
// (host shadow address != device address; on GB300 ATS makes that a silent
// wrong-memory write, not a fault).
__global__ void prop_kernel(const float* __restrict__ x_in, int step,
                            const int* __restrict__ row,
                            const int* __restrict__ col, int E) {
    const float* src = (step == 0) ? x_in : (step == 1 ? g_T1 : g_T2);
    float*       dst = (step == 0) ? g_T1 : (step == 1 ? g_T2 : g_T3);

    long long tid = (long long)blockIdx.x * blockDim.x + threadIdx.x;
    int e  = (int)(tid >> 4);
    int ch = ((int)tid & 15) << 2;
    if (e >= E) return;
    int r = row[e], c = col[e];
    float nm = g_norm[e];
    float4 v = *reinterpret_cast<const float4*>(src + (size_t)c * C + ch);
    v.x *= nm; v.y *= nm; v.z *= nm; v.w *= nm;
    float* p = dst + (size_t)r * C + ch;
    asm volatile("red.global.add.v4.f32 [%0], {%1, %2, %3, %4};"
                 :: "l"(p), "f"(v.x), "f"(v.y), "f"(v.z), "f"(v.w)
                 : "memory");
}

// -------- fused epilogue: out = x@W0 + T1@W1 + T2@W2 + T3@W3 ----------------
// One warp per node row; lane j computes output columns (2j, 2j+1).
__global__ void out_gemm_kernel(const float* __restrict__ x,
                                float* __restrict__ out, int n_nodes) {
    int warp = threadIdx.x >> 5;
    int lane = threadIdx.x & 31;
    int rowi = blockIdx.x * 8 + warp;
    if (rowi >= n_nodes) return;

    const float* srcs[4] = {x, g_T1, g_T2, g_T3};
    float acc0 = 0.f, acc1 = 0.f;

#pragma unroll
    for (int s = 0; s < 4; s++) {
        const float* rp = srcs[s] + (size_t)rowi * C;
        float a0 = rp[lane];        // k = lane
        float a1 = rp[lane + 32];   // k = lane + 32
        const float* Wp = g_W + s * C * C;
#pragma unroll
        for (int k = 0; k < 32; k++) {
            float xv = __shfl_sync(0xffffffffu, a0, k);
            float2 w = *reinterpret_cast<const float2*>(Wp + k * C + 2 * lane);
            acc0 = fmaf(xv, w.x, acc0);
            acc1 = fmaf(xv, w.y, acc1);
        }
#pragma unroll
        for (int k = 0; k < 32; k++) {
            float xv = __shfl_sync(0xffffffffu, a1, k);
            float2 w = *reinterpret_cast<const float2*>(Wp + (k + 32) * C + 2 * lane);
            acc0 = fmaf(xv, w.x, acc0);
            acc1 = fmaf(xv, w.y, acc1);
        }
    }
    float2 r = make_float2(acc0, acc1);
    *reinterpret_cast<float2*>(out + (size_t)rowi * C + 2 * lane) = r;
}

// ============================================================================
extern "C" void kernel_launch(void* const* d_in, const int* in_sizes, int n_in,
                              void* d_out, int out_size) {
    const float* x  = (const float*)d_in[0];           // [N, 64]
    const int*   ei = (const int*)d_in[1];             // [2, E]
    const float* ew = (const float*)d_in[2];           // [E]
    const float* tf = (const float*)d_in[3];           // [3, 64, 64]
    const float* tb = (const float*)d_in[4];           // [3, 64, 64]
    float* out = (float*)d_out;

    const int N = in_sizes[0] / C;                     // 50000
    const int E = in_sizes[2];                         // 800000
    const int* row = ei;
    const int* col = ei + E;

    // 1. zero scratch
    zero_kernel<<<1184, 256>>>(N);

    // 2. degree + norm precompute
    deg_kernel<<<(E + 255) / 256, 256>>>(row, ew, E);
    dinv_kernel<<<(N + 255) / 256, 256>>>(N);
    norm_kernel<<<(E + 255) / 256, 256>>>(row, col, ew, E);
    wprep_kernel<<<(C * C + 255) / 256, 256>>>(tf, tb);

    // 3. three diffusion steps (scratch selected device-side via step index)
    long long prop_threads = (long long)E * 16;
    int prop_blocks = (int)((prop_threads + 255) / 256);
    prop_kernel<<<prop_blocks, 256>>>(x, 0, row, col, E);
    prop_kernel<<<prop_blocks, 256>>>(x, 1, row, col, E);
    prop_kernel<<<prop_blocks, 256>>>(x, 2, row, col, E);

    // 4. fused 4-way GEMM epilogue
    out_gemm_kernel<<<(N + 7) / 8, 256>>>(x, out, N);
}

// round 7
// speedup vs baseline: 1.9776x; 1.9776x over previous
#include <cuda_runtime.h>
#include <cuda_bf16.h>
#include <cstdint>

// Problem constants (DiffusionConv: N=50000, E=800000, C=64, K=3)
#define NMAX 50000
#define EMAX 800000
#define C    64

// -------- device scratch (no allocs allowed) --------
__device__ float g_T1[NMAX * C];
__device__ float g_T2[NMAX * C];
__device__ float g_T3[NMAX * C];
__device__ float g_deg[NMAX];
__device__ float g_dinv[NMAX];
__device__ float g_W[4 * C * C];       // W0=Tf0, W1=Tb0+Tb1, W2=Tf1+Tb2, W3=Tf2

// CSR scratch (rebuilt every call; deterministic content up to fp-add order)
__device__ int   g_cnt[NMAX];          // per-row edge count
__device__ int   g_rowptr[NMAX + 1];
__device__ int   g_cur[NMAX];          // scatter cursors
__device__ int   g_bsum[128];          // block partial sums for scan
__device__ int   g_ecol[EMAX];         // CSR: col index per edge
__device__ float g_enorm[EMAX];        // CSR: dinv[r]*w*dinv[c] per edge

// ---------------- packed fp32x2 helpers ----------------
#define FMA2(d, a, b) \
    asm("fma.rn.f32x2 %0, %1, %2, %3;" : "=l"(d) : "l"(a), "l"(b), "l"(d))

// ---------------- tiny init: zero cnt + deg ----------------
__global__ void init_zero_kernel(int N) {
    int i = blockIdx.x * blockDim.x + threadIdx.x;
    if (i < N) { g_cnt[i] = 0; g_deg[i] = 0.f; }
}

// ---------------- degree + histogram in one pass ----------------
__global__ void deg_hist_kernel(const int* __restrict__ row,
                                const float* __restrict__ w, int E) {
    int e = blockIdx.x * blockDim.x + threadIdx.x;
    if (e < E) {
        int r = row[e];
        atomicAdd(&g_deg[r], w[e]);
        atomicAdd(&g_cnt[r], 1);
    }
}

__global__ void dinv_kernel(int N) {
    int i = blockIdx.x * blockDim.x + threadIdx.x;
    if (i < N) {
        float d = g_deg[i];
        g_dinv[i] = (d > 0.f) ? rsqrtf(d) : 0.f;
    }
}

// ---------------- exclusive scan of g_cnt -> g_rowptr (3 kernels) ----------
__global__ void scan1_kernel(int N) {            // 512-thread blocks
    __shared__ int s[512];
    int tid = threadIdx.x;
    int i = blockIdx.x * 512 + tid;
    int v = (i < N) ? g_cnt[i] : 0;
    s[tid] = v;
    __syncthreads();
#pragma unroll
    for (int off = 1; off < 512; off <<= 1) {
        int t = (tid >= off) ? s[tid - off] : 0;
        __syncthreads();
        s[tid] += t;
        __syncthreads();
    }
    if (i < N) g_rowptr[i] = s[tid] - v;         // block-local exclusive
    if (tid == 511) g_bsum[blockIdx.x] = s[511]; // block total
}

__global__ void scan2_kernel(int nb) {           // single block, 128 threads
    __shared__ int s[128];
    int tid = threadIdx.x;
    int v = (tid < nb) ? g_bsum[tid] : 0;
    s[tid] = v;
    __syncthreads();
#pragma unroll
    for (int off = 1; off < 128; off <<= 1) {
        int t = (tid >= off) ? s[tid - off] : 0;
        __syncthreads();
        s[tid] += t;
        __syncthreads();
    }
    if (tid < nb) g_bsum[tid] = s[tid] - v;      // exclusive
}

__global__ void scan3_kernel(int N, int E) {
    int i = blockIdx.x * 512 + threadIdx.x;
    if (i < N) {
        int rp = g_rowptr[i] + g_bsum[blockIdx.x];
        g_rowptr[i] = rp;
        g_cur[i] = rp;
    }
    if (i == 0) g_rowptr[N] = E;
}

// ---------------- scatter edges into CSR (norm fused) ----------------
__global__ void scatter_kernel(const int* __restrict__ row,
                               const int* __restrict__ col,
                               const float* __restrict__ w, int E) {
    int e = blockIdx.x * blockDim.x + threadIdx.x;
    if (e < E) {
        int r = row[e], c = col[e];
        float nm = g_dinv[r] * w[e] * g_dinv[c];
        int pos = atomicAdd(&g_cur[r], 1);
        g_ecol[pos] = c;
        g_enorm[pos] = nm;
    }
}

// ---------------- combine thetas ----------------
__global__ void wprep_kernel(const float* __restrict__ tf,
                             const float* __restrict__ tb) {
    int i = blockIdx.x * blockDim.x + threadIdx.x;
    if (i < C * C) {
        g_W[0 * C * C + i] = tf[0 * C * C + i];
        g_W[1 * C * C + i] = tb[0 * C * C + i] + tb[1 * C * C + i];
        g_W[2 * C * C + i] = tf[1 * C * C + i] + tb[2 * C * C + i];
        g_W[3 * C * C + i] = tf[2 * C * C + i];
    }
}

// ---------------- propagate via CSR gather: one warp per node -------------
// No atomics: each warp accumulates its node's row in registers, writes once.
// src/dst selected device-side by step (never pass __device__ symbols from host).
__global__ void prop_csr_kernel(const float* __restrict__ x_in, int step, int N) {
    const float* __restrict__ src =
        (step == 0) ? x_in : (step == 1 ? g_T1 : g_T2);
    float* __restrict__ dst =
        (step == 0) ? g_T1 : (step == 1 ? g_T2 : g_T3);

    int warp = (int)((blockIdx.x * blockDim.x + threadIdx.x) >> 5);
    if (warp >= N) return;
    int lane = threadIdx.x & 31;

    int beg = g_rowptr[warp];
    int end = g_rowptr[warp + 1];

    float ax = 0.f, ay = 0.f;
    int e = beg;
    // unroll-4 for MLP within the warp
    for (; e + 4 <= end; e += 4) {
        int c0 = g_ecol[e + 0], c1 = g_ecol[e + 1];
        int c2 = g_ecol[e + 2], c3 = g_ecol[e + 3];
        float n0 = g_enorm[e + 0], n1 = g_enorm[e + 1];
        float n2 = g_enorm[e + 2], n3 = g_enorm[e + 3];
        float2 v0 = *(const float2*)(src + ((size_t)c0 << 6) + (lane << 1));
        float2 v1 = *(const float2*)(src + ((size_t)c1 << 6) + (lane << 1));
        float2 v2 = *(const float2*)(src + ((size_t)c2 << 6) + (lane << 1));
        float2 v3 = *(const float2*)(src + ((size_t)c3 << 6) + (lane << 1));
        ax = fmaf(n0, v0.x, ax); ay = fmaf(n0, v0.y, ay);
        ax = fmaf(n1, v1.x, ax); ay = fmaf(n1, v1.y, ay);
        ax = fmaf(n2, v2.x, ax); ay = fmaf(n2, v2.y, ay);
        ax = fmaf(n3, v3.x, ax); ay = fmaf(n3, v3.y, ay);
    }
    for (; e < end; e++) {
        int c = g_ecol[e];
        float nm = g_enorm[e];
        float2 v = *(const float2*)(src + ((size_t)c << 6) + (lane << 1));
        ax = fmaf(nm, v.x, ax); ay = fmaf(nm, v.y, ay);
    }
    *(float2*)(dst + ((size_t)warp << 6) + (lane << 1)) = make_float2(ax, ay);
}

// ---------------- fused epilogue GEMM: out = sum_s A_s @ W_s ----------------
// BM=128 rows/block, 256 threads. Thread tile: 8 rows x 4 cols.
// W_s staged to smem (16KB); A_s staged k-major transposed in 32-k halves
// so adjacent-row pairs load directly as packed f32x2 operands.
#define BM 128
__global__ void out_gemm_kernel(const float* __restrict__ x,
                                float* __restrict__ out, int N) {
    __shared__ float sW[64 * 64];        // 16 KB, one src at a time
    __shared__ float sA[32 * 130];       // 16.25 KB, k-major, row-pair friendly

    int t = threadIdx.x;
    int tx = t & 15;                     // col group: cols tx*4 .. tx*4+3
    int ty = t >> 4;                     // row group: rows ty*8 .. ty*8+7
    int row0 = blockIdx.x * BM;
    int rbase = ty * 8;

    unsigned long long acc[4][4];        // [row-pair p][col c] packed fp32x2
#pragma unroll
    for (int p = 0; p < 4; p++)
#pragma unroll
        for (int c = 0; c < 4; c++) acc[p][c] = 0ull;

#pragma unroll
    for (int s = 0; s < 4; s++) {
        const float* __restrict__ As =
            (s == 0) ? x : (s == 1 ? g_T1 : (s == 2 ? g_T2 : g_T3));

        __syncthreads();   // previous iteration done reading sW/sA
        // stage W_s (coalesced float4)
        {
            const float4* Wg = (const float4*)(g_W + s * 64 * 64);
            float4* Ws4 = (float4*)sW;
            for (int i = t; i < 1024; i += 256) Ws4[i] = Wg[i];
        }

        for (int kh = 0; kh < 2; kh++) {
            __syncthreads();  // done reading sA from previous half / sW staged
            // stage A rows [row0, row0+128), k in [kh*32, kh*32+32), transposed
#pragma unroll
            for (int it = 0; it < 4; it++) {
                int idx = it * 256 + t;          // 0..1023
                int r = idx >> 3;                // 0..127
                int kc = (idx & 7) << 2;         // 0,4,...,28 (local k)
                float4 v = make_float4(0.f, 0.f, 0.f, 0.f);
                int gr = row0 + r;
                if (gr < N)
                    v = *(const float4*)(As + (size_t)gr * 64 + kh * 32 + kc);
                sA[(kc + 0) * 130 + r] = v.x;
                sA[(kc + 1) * 130 + r] = v.y;
                sA[(kc + 2) * 130 + r] = v.z;
                sA[(kc + 3) * 130 + r] = v.w;
            }
            __syncthreads();
            // compute this 32-k half
#pragma unroll
            for (int k4 = 0; k4 < 8; k4++) {
#pragma unroll
                for (int kk = 0; kk < 4; kk++) {
                    int kl = k4 * 4 + kk;
                    float4 w4 = *(const float4*)&sW[(kh * 32 + kl) * 64 + tx * 4];
                    unsigned long long wp0, wp1, wp2, wp3;
                    unsigned int u0 = __float_as_uint(w4.x);
                    unsigned int u1 = __float_as_uint(w4.y);
                    unsigned int u2 = __float_as_uint(w4.z);
                    unsigned int u3 = __float_as_uint(w4.w);
                    asm("mov.b64 %0,{%1,%1};" : "=l"(wp0) : "r"(u0));
                    asm("mov.b64 %0,{%1,%1};" : "=l"(wp1) : "r"(u1));
                    asm("mov.b64 %0,{%1,%1};" : "=l"(wp2) : "r"(u2));
                    asm("mov.b64 %0,{%1,%1};" : "=l"(wp3) : "r"(u3));
                    const unsigned long long* ap =
                        (const unsigned long long*)&sA[kl * 130 + rbase];
                    unsigned long long a0 = ap[0], a1 = ap[1];
                    unsigned long long a2 = ap[2], a3 = ap[3];
                    FMA2(acc[0][0], a0, wp0); FMA2(acc[0][1], a0, wp1);
                    FMA2(acc[0][2], a0, wp2); FMA2(acc[0][3], a0, wp3);
                    FMA2(acc[1][0], a1, wp0); FMA2(acc[1][1], a1, wp1);
                    FMA2(acc[1][2], a1, wp2); FMA2(acc[1][3], a1, wp3);
                    FMA2(acc[2][0], a2, wp0); FMA2(acc[2][1], a2, wp1);
                    FMA2(acc[2][2], a2, wp2); FMA2(acc[2][3], a2, wp3);
                    FMA2(acc[3][0], a3, wp0); FMA2(acc[3][1], a3, wp1);
                    FMA2(acc[3][2], a3, wp2); FMA2(acc[3][3], a3, wp3);
                }
            }
        }
    }

    // writeout: unpack pairs; lo = even row, hi = odd row
#pragma unroll
    for (int p = 0; p < 4; p++) {
        unsigned int lo[4], hi[4];
#pragma unroll
        for (int c = 0; c < 4; c++)
            asm("mov.b64 {%0,%1},%2;" : "=r"(lo[c]), "=r"(hi[c]) : "l"(acc[p][c]));
        int r_lo = row0 + rbase + 2 * p;
        if (r_lo < N) {
            float4 v = make_float4(__uint_as_float(lo[0]), __uint_as_float(lo[1]),
                                   __uint_as_float(lo[2]), __uint_as_float(lo[3]));
            *(float4*)(out + (size_t)r_lo * 64 + tx * 4) = v;
        }
        int r_hi = r_lo + 1;
        if (r_hi < N) {
            float4 v = make_float4(__uint_as_float(hi[0]), __uint_as_float(hi[1]),
                                   __uint_as_float(hi[2]), __uint_as_float(hi[3]));
            *(float4*)(out + (size_t)r_hi * 64 + tx * 4) = v;
        }
    }
}

// ============================================================================
extern "C" void kernel_launch(void* const* d_in, const int* in_sizes, int n_in,
                              void* d_out, int out_size) {
    const float* x  = (const float*)d_in[0];           // [N, 64]
    const int*   ei = (const int*)d_in[1];             // [2, E]
    const float* ew = (const float*)d_in[2];           // [E]
    const float* tf = (const float*)d_in[3];           // [3, 64, 64]
    const float* tb = (const float*)d_in[4];           // [3, 64, 64]
    float* out = (float*)d_out;

    const int N = in_sizes[0] / C;                     // 50000
    const int E = in_sizes[2];                         // 800000
    const int* row = ei;
    const int* col = ei + E;

    const int nb512 = (N + 511) / 512;                 // 98 scan blocks

    // 1. tiny init (cnt + deg only; T buffers fully overwritten by gather)
    init_zero_kernel<<<(N + 255) / 256, 256>>>(N);

    // 2. degree + histogram, dinv
    deg_hist_kernel<<<(E + 255) / 256, 256>>>(row, ew, E);
    dinv_kernel<<<(N + 255) / 256, 256>>>(N);

    // 3. exclusive scan -> rowptr, cursors
    scan1_kernel<<<nb512, 512>>>(N);
    scan2_kernel<<<1, 128>>>(nb512);
    scan3_kernel<<<nb512, 512>>>(N, E);

    // 4. CSR scatter (norm fused) + weight fold
    scatter_kernel<<<(E + 255) / 256, 256>>>(row, col, ew, E);
    wprep_kernel<<<(C * C + 255) / 256, 256>>>(tf, tb);

    // 5. three diffusion steps (gather, no atomics): one warp per node
    int prop_blocks = (N + 7) / 8;                     // 8 warps per 256-thr block
    prop_csr_kernel<<<prop_blocks, 256>>>(x, 0, N);
    prop_csr_kernel<<<prop_blocks, 256>>>(x, 1, N);
    prop_csr_kernel<<<prop_blocks, 256>>>(x, 2, N);

    // 6. fused 4-way GEMM epilogue (fp32x2 packed FMA)
    out_gemm_kernel<<<(N + BM - 1) / BM, 256>>>(x, out, N);
}